// round 3
// baseline (speedup 1.0000x reference)
#include <cuda_runtime.h>
#include <math.h>

#define B_ 128
#define T_ 512
#define D_ 256
#define U_ 512
#define O_ 64
#define J_ 2048      /* 4*U */
#define K_ 768       /* U + D */

// ---------------- device scratch (static, no allocation) ----------------
__device__ float g_Wfold[K_ * J_];            // [768][2048]: rows 0..511 = rec + dw@Wt, 512..767 = Wx
__device__ float g_B0[J_];                    // bias for t==0
__device__ float g_BT[J_];                    // bias + dense_b@Wt for t>=1
__device__ float g_H[2][B_ * U_];             // double-buffered hidden state
__device__ float g_Hall[(size_t)T_ * B_ * U_];// all h_t for the final dense GEMM (134 MB)
__device__ unsigned g_barCount;
__device__ volatile unsigned g_barPhase;

// ---------------- prep: fold weights ----------------
__global__ void prep_weights(const float* __restrict__ rec,
                             const float* __restrict__ kern,
                             const float* __restrict__ dw) {
    int idx = blockIdx.x * 256 + threadIdx.x;      // 768*2048 total
    int r = idx >> 11;
    int j = idx & 2047;
    float v;
    if (r < U_) {
        v = rec[r * J_ + j];
#pragma unroll 8
        for (int o = 0; o < O_; o++)
            v += dw[r * O_ + o] * kern[(D_ + o) * J_ + j];
    } else {
        v = kern[(r - U_) * J_ + j];
    }
    g_Wfold[idx] = v;
}

// ---------------- prep: biases, zero h0, reset barrier ----------------
__global__ void prep_misc(const float* __restrict__ bias,
                          const float* __restrict__ db,
                          const float* __restrict__ kern) {
    int idx = blockIdx.x * 256 + threadIdx.x;
    if (idx < J_) {
        float b0 = bias[idx];
        float bt = b0;
#pragma unroll 8
        for (int o = 0; o < O_; o++)
            bt += db[o] * kern[(D_ + o) * J_ + idx];
        g_B0[idx] = b0;
        g_BT[idx] = bt;
    } else if (idx < J_ + B_ * U_) {
        g_H[0][idx - J_] = 0.f;
    } else if (idx == J_ + B_ * U_) {
        g_barCount = 0u;
        g_barPhase = 0u;
    }
}

// ---------------- persistent recurrent kernel ----------------
// grid = 128 CTAs (8 b-tiles x 16 u-tiles), 256 threads, 1 CTA/SM -> co-resident.
// CTA tile: 16 b x 32 u x 4 gates = 2048 z-outputs.
// Thread: bg = tid>>6 (4 b's: bg*4..+3), lane64 = tid&63 -> jj = 2*lane64 (2 adjacent
// logical columns, logical col jl = g*32+ul maps to weight col g*512 + ut*32 + ul).
#define KSTEP(HC, PWOFF) do {                                   \
    float2 w_ = *(const float2*)(pw + (PWOFF));                 \
    a00 += h0.HC * w_.x; a01 += h0.HC * w_.y;                   \
    a10 += h1.HC * w_.x; a11 += h1.HC * w_.y;                   \
    a20 += h2.HC * w_.x; a21 += h2.HC * w_.y;                   \
    a30 += h3.HC * w_.x; a31 += h3.HC * w_.y;                   \
} while (0)

__global__ __launch_bounds__(256, 1) void lstm_recur(const float* __restrict__ inp) {
    extern __shared__ float sm[];
    float* hs = sm;                       // [16][768] staged [h_t | x_t]
    float* zs = sm + 16 * K_;             // [16][132] z tile (padded)
    float* cs = zs + 16 * 132;            // [512] per-CTA cell state (persistent)

    const int tid = threadIdx.x;
    const int bt = blockIdx.x >> 4;       // 0..7
    const int ut = blockIdx.x & 15;       // 0..15
    const int lane64 = tid & 63;
    const int bg = tid >> 6;              // 0..3
    const int jj = lane64 * 2;            // logical col pair base (even)
    const int gg = jj >> 5;               // gate of this column pair
    const int ul2 = jj & 31;
    const int jcol = gg * U_ + ut * 32 + ul2;   // weight column (jcol, jcol+1)
    const float* const pW = g_Wfold + jcol;

    cs[tid] = 0.f;
    cs[tid + 256] = 0.f;

    for (int t = 0; t < T_; t++) {
        // ---- stage hs = [h_t (512) | x_t (256)] for our 16 batch rows ----
        // 16 rows x 192 float4 = 3072 float4 loads. h via __ldcg (L1 not coherent
        // across SMs; these lines were written by other CTAs last step).
        for (int idx = tid; idx < 3072; idx += 256) {
            int bl = idx / 192;
            int off = idx - bl * 192;
            float4 v;
            if (off < 128) {
                v = __ldcg((const float4*)&g_H[t & 1][(bt * 16 + bl) * U_ + off * 4]);
            } else {
                v = *(const float4*)&inp[((bt * 16 + bl) * T_ + t) * D_ + (off - 128) * 4];
            }
            *(float4*)&hs[bl * K_ + off * 4] = v;
        }
        __syncthreads();

        // ---- GEMM: z[16][128] = hs[16][768] @ W'[768][(4 gates x 32 u)] ----
        float a00 = 0, a01 = 0, a10 = 0, a11 = 0, a20 = 0, a21 = 0, a30 = 0, a31 = 0;
        const float* ph = hs + bg * 4 * K_;
        const float* pw = pW;
#pragma unroll 2
        for (int k = 0; k < K_; k += 4) {
            float4 h0 = *(const float4*)(ph + k);
            float4 h1 = *(const float4*)(ph + K_ + k);
            float4 h2 = *(const float4*)(ph + 2 * K_ + k);
            float4 h3 = *(const float4*)(ph + 3 * K_ + k);
            KSTEP(x, 0);
            KSTEP(y, J_);
            KSTEP(z, 2 * J_);
            KSTEP(w, 3 * J_);
            pw += 4 * J_;
        }
        // write z tile to smem (padded stride 132, float2 stores, even offsets)
        *(float2*)&zs[(bg * 4 + 0) * 132 + jj] = make_float2(a00, a01);
        *(float2*)&zs[(bg * 4 + 1) * 132 + jj] = make_float2(a10, a11);
        *(float2*)&zs[(bg * 4 + 2) * 132 + jj] = make_float2(a20, a21);
        *(float2*)&zs[(bg * 4 + 3) * 132 + jj] = make_float2(a30, a31);
        __syncthreads();

        // ---- gates + state update: 2 cells per thread ----
        const float* bv = (t == 0) ? g_B0 : g_BT;
#pragma unroll
        for (int s = 0; s < 2; s++) {
            int cell = tid + s * 256;             // 0..511
            int bl = cell >> 5;
            int ul = cell & 31;
            const float* zr = zs + bl * 132 + ul;
            int jb = ut * 32 + ul;
            float zi = zr[0]  + bv[jb];
            float zf = zr[32] + bv[U_ + jb];
            float zg = zr[64] + bv[2 * U_ + jb];
            float zo = zr[96] + bv[3 * U_ + jb];
            float ig = 1.f / (1.f + expf(-zi));
            float fg = 1.f / (1.f + expf(-zf));
            float gv = tanhf(zg);
            float og = 1.f / (1.f + expf(-zo));
            float cn = fg * cs[cell] + ig * gv;
            cs[cell] = cn;
            float hn = og * tanhf(cn);
            int bglob = bt * 16 + bl;
            int uglob = ut * 32 + ul;
            g_H[(t + 1) & 1][bglob * U_ + uglob] = hn;
            g_Hall[((size_t)t * B_ + bglob) * U_ + uglob] = hn;
        }

        // ---- grid barrier (phase = t+1, monotonic count, reset by prep) ----
        __threadfence();          // publish h writes to L2 before arriving
        __syncthreads();
        if (tid == 0) {
            unsigned old = atomicAdd(&g_barCount, 1u);
            if (old == (unsigned)(128 * (t + 1) - 1)) {
                g_barPhase = (unsigned)(t + 1);   // release
            } else {
                while (g_barPhase < (unsigned)(t + 1)) { }
            }
            __threadfence();
        }
        __syncthreads();
    }
}

// ---------------- final dense: out[b][t][o] = Hall[t][b] @ dense_w + db ----
__global__ __launch_bounds__(256) void dense_out_k(const float* __restrict__ dw,
                                                   const float* __restrict__ db,
                                                   float* __restrict__ out) {
    __shared__ float hT[32 * 72];   // [32 b][64 k] padded stride 72
    __shared__ float wT[64 * 64];   // [64 k][64 o]
    int t = blockIdx.x;
    int b0 = blockIdx.y * 32;
    int tid = threadIdx.x;
    int ol = tid & 31;
    int bg = tid >> 5;              // 0..7 -> 4 b's each
    float a00 = 0, a01 = 0, a10 = 0, a11 = 0, a20 = 0, a21 = 0, a30 = 0, a31 = 0;

    for (int k0 = 0; k0 < U_; k0 += 64) {
        int idx = tid;
#pragma unroll
        for (int it = 0; it < 2; it++, idx += 256) {      // 512 float4: hT
            int bl = idx >> 4;
            int kk = (idx & 15) * 4;
            float4 v = *(const float4*)&g_Hall[((size_t)t * B_ + b0 + bl) * U_ + k0 + kk];
            *(float4*)&hT[bl * 72 + kk] = v;
        }
        idx = tid;
#pragma unroll
        for (int it = 0; it < 4; it++, idx += 256) {      // 1024 float4: wT
            int kk = idx >> 4;
            int oo = (idx & 15) * 4;
            float4 v = *(const float4*)&dw[(k0 + kk) * O_ + oo];
            *(float4*)&wT[kk * 64 + oo] = v;
        }
        __syncthreads();
#pragma unroll 4
        for (int k = 0; k < 64; k++) {
            float w0 = wT[k * 64 + ol];
            float w1 = wT[k * 64 + ol + 32];
            float h0 = hT[(bg * 4 + 0) * 72 + k];
            float h1 = hT[(bg * 4 + 1) * 72 + k];
            float h2 = hT[(bg * 4 + 2) * 72 + k];
            float h3 = hT[(bg * 4 + 3) * 72 + k];
            a00 += h0 * w0; a01 += h0 * w1;
            a10 += h1 * w0; a11 += h1 * w1;
            a20 += h2 * w0; a21 += h2 * w1;
            a30 += h3 * w0; a31 += h3 * w1;
        }
        __syncthreads();
    }
    float d0 = db[ol], d1 = db[ol + 32];
    int b = b0 + bg * 4;
    out[((size_t)(b + 0) * T_ + t) * O_ + ol]      = a00 + d0;
    out[((size_t)(b + 0) * T_ + t) * O_ + ol + 32] = a01 + d1;
    out[((size_t)(b + 1) * T_ + t) * O_ + ol]      = a10 + d0;
    out[((size_t)(b + 1) * T_ + t) * O_ + ol + 32] = a11 + d1;
    out[((size_t)(b + 2) * T_ + t) * O_ + ol]      = a20 + d0;
    out[((size_t)(b + 2) * T_ + t) * O_ + ol + 32] = a21 + d1;
    out[((size_t)(b + 3) * T_ + t) * O_ + ol]      = a30 + d0;
    out[((size_t)(b + 3) * T_ + t) * O_ + ol + 32] = a31 + d1;
}

// ---------------- launch ----------------
extern "C" void kernel_launch(void* const* d_in, const int* in_sizes, int n_in,
                              void* d_out, int out_size) {
    const float* inputs = (const float*)d_in[0];   // [128][512][256]
    const float* kern   = (const float*)d_in[1];   // [320][2048]
    const float* rec    = (const float*)d_in[2];   // [512][2048]
    const float* bias   = (const float*)d_in[3];   // [2048]
    const float* dw     = (const float*)d_in[4];   // [512][64]
    const float* db     = (const float*)d_in[5];   // [64]
    float* out = (float*)d_out;                    // [128][512][64]

    const size_t smem = (size_t)(16 * K_ + 16 * 132 + 512) * sizeof(float); // 59648 B
    cudaFuncSetAttribute(lstm_recur, cudaFuncAttributeMaxDynamicSharedMemorySize, (int)smem);

    prep_weights<<<(K_ * J_) / 256, 256>>>(rec, kern, dw);
    prep_misc<<<(J_ + B_ * U_ + 1 + 255) / 256, 256>>>(bias, db, kern);
    lstm_recur<<<128, 256, smem>>>(inputs);
    dense_out_k<<<dim3(T_, 4), 256>>>(dw, db, out);
}

// round 12
// speedup vs baseline: 1.4553x; 1.4553x over previous
#include <cuda_runtime.h>
#include <math.h>

#define B_ 128
#define T_ 512
#define D_ 256
#define U_ 512
#define O_ 64
#define J_ 2048      /* 4*U */
#define K_ 768       /* U + D */

typedef unsigned long long ull;

// ---------------- device scratch (static, no allocation) ----------------
__device__ float g_Wfold[K_ * J_];            // [768][2048]
__device__ float g_B0[J_];
__device__ float g_BT[J_];
__device__ float g_H[2][B_ * U_];
__device__ float g_Hall[(size_t)T_ * B_ * U_];
__device__ unsigned g_barCount;
__device__ volatile unsigned g_barPhase;

// ---------------- f32x2 helpers ----------------
__device__ __forceinline__ ull dupf(float x) {
    ull p;
    asm("mov.b64 %0, {%1, %1};" : "=l"(p) : "f"(x));
    return p;
}
__device__ __forceinline__ void ffma2(ull& d, ull a, ull b) {
    asm("fma.rn.f32x2 %0, %1, %2, %0;" : "+l"(d) : "l"(a), "l"(b));
}

// ---------------- prep: fold weights ----------------
__global__ void prep_weights(const float* __restrict__ rec,
                             const float* __restrict__ kern,
                             const float* __restrict__ dw) {
    int idx = blockIdx.x * 256 + threadIdx.x;
    int r = idx >> 11;
    int j = idx & 2047;
    float v;
    if (r < U_) {
        v = rec[r * J_ + j];
#pragma unroll 8
        for (int o = 0; o < O_; o++)
            v += dw[r * O_ + o] * kern[(D_ + o) * J_ + j];
    } else {
        v = kern[(r - U_) * J_ + j];
    }
    g_Wfold[idx] = v;
}

__global__ void prep_misc(const float* __restrict__ bias,
                          const float* __restrict__ db,
                          const float* __restrict__ kern) {
    int idx = blockIdx.x * 256 + threadIdx.x;
    if (idx < J_) {
        float b0 = bias[idx];
        float bt = b0;
#pragma unroll 8
        for (int o = 0; o < O_; o++)
            bt += db[o] * kern[(D_ + o) * J_ + idx];
        g_B0[idx] = b0;
        g_BT[idx] = bt;
    } else if (idx < J_ + B_ * U_) {
        g_H[0][idx - J_] = 0.f;
    } else if (idx == J_ + B_ * U_) {
        g_barCount = 0u;
        g_barPhase = 0u;
    }
}

// ---------------- persistent recurrent kernel ----------------
// grid = 128 CTAs (8 b-tiles x 16 u-tiles), 256 threads, 1 CTA/SM.
// CTA tile: 16 b x 128 cols (4 gates x 32 u) x 768 k.
// Thread: ks = tid>>6 (k-split 4, 192 k each); cg = (tid&63)&15 -> 8 contiguous
// weight cols (gate = cg>>2, sub = (cg&3)*8); bg = (tid&63)>>4 -> 4 b rows.
// Accumulate in f32x2 pairs over adjacent columns: 4 col-pairs x 4 b = 16 b64 accs.

#define CKSTEP(WAI, WBI, COMP) do {                                    \
    ull d0 = dupf(h0v.COMP), d1 = dupf(h1v.COMP);                      \
    ull d2 = dupf(h2v.COMP), d3 = dupf(h3v.COMP);                      \
    ffma2(a00, d0, WAI.x); ffma2(a01, d0, WAI.y);                      \
    ffma2(a02, d0, WBI.x); ffma2(a03, d0, WBI.y);                      \
    ffma2(a10, d1, WAI.x); ffma2(a11, d1, WAI.y);                      \
    ffma2(a12, d1, WBI.x); ffma2(a13, d1, WBI.y);                      \
    ffma2(a20, d2, WAI.x); ffma2(a21, d2, WAI.y);                      \
    ffma2(a22, d2, WBI.x); ffma2(a23, d2, WBI.y);                      \
    ffma2(a30, d3, WAI.x); ffma2(a31, d3, WAI.y);                      \
    ffma2(a32, d3, WBI.x); ffma2(a33, d3, WBI.y);                      \
} while (0)

__global__ __launch_bounds__(256, 1) void lstm_recur(const float* __restrict__ inp) {
    extern __shared__ float sm[];
    float* hs   = sm;                       // [16][768] staged [h_t | x_t]
    float* zred = sm + 16 * K_;             // [4 ks][16 b][128 col] partials
    float* cs   = zred + 4 * 16 * 128;      // [512] per-CTA cell state

    const int tid = threadIdx.x;
    const int bt = blockIdx.x >> 4;         // 0..7
    const int ut = blockIdx.x & 15;         // 0..15
    const int ks = tid >> 6;                // 0..3
    const int t64 = tid & 63;
    const int cg = t64 & 15;                // 0..15
    const int bg = t64 >> 4;                // 0..3
    const int gate = cg >> 2;
    const int colsub = (cg & 3) * 8;
    const int physcol = gate * U_ + ut * 32 + colsub;  // 8 contiguous weight cols
    const int lcol = gate * 32 + colsub;               // logical col in CTA tile
    const int k0 = ks * 192;

    cs[tid] = 0.f;
    cs[tid + 256] = 0.f;

    const float* const Wbase = g_Wfold + (size_t)k0 * J_ + physcol;

    for (int t = 0; t < T_; t++) {
        // ---- stage hs = [h_t (512) | x_t (256)] for our 16 batch rows ----
        for (int idx = tid; idx < 3072; idx += 256) {
            int bl = idx / 192;
            int off = idx - bl * 192;
            float4 v;
            if (off < 128) {
                v = __ldcg((const float4*)&g_H[t & 1][(bt * 16 + bl) * U_ + off * 4]);
            } else {
                v = *(const float4*)&inp[((bt * 16 + bl) * T_ + t) * D_ + (off - 128) * 4];
            }
            *(float4*)&hs[bl * K_ + off * 4] = v;
        }
        __syncthreads();

        // ---- GEMM partial: 4 b x 8 cols x 192 k, f32x2 packed ----
        ull a00 = 0, a01 = 0, a02 = 0, a03 = 0;
        ull a10 = 0, a11 = 0, a12 = 0, a13 = 0;
        ull a20 = 0, a21 = 0, a22 = 0, a23 = 0;
        ull a30 = 0, a31 = 0, a32 = 0, a33 = 0;

        const float* pw = Wbase;
        const float* ph = hs + bg * 4 * K_ + k0;

        // preload weight group 0 (4 k-rows x 8 cols)
        ulonglong2 wa0 = *(const ulonglong2*)(pw);
        ulonglong2 wb0 = *(const ulonglong2*)(pw + 4);
        ulonglong2 wa1 = *(const ulonglong2*)(pw + J_);
        ulonglong2 wb1 = *(const ulonglong2*)(pw + J_ + 4);
        ulonglong2 wa2 = *(const ulonglong2*)(pw + 2 * J_);
        ulonglong2 wb2 = *(const ulonglong2*)(pw + 2 * J_ + 4);
        ulonglong2 wa3 = *(const ulonglong2*)(pw + 3 * J_);
        ulonglong2 wb3 = *(const ulonglong2*)(pw + 3 * J_ + 4);

#pragma unroll 1
        for (int g = 0; g < 48; g++) {
            // h for this 4-k group, 4 b rows
            float4 h0v = *(const float4*)(ph);
            float4 h1v = *(const float4*)(ph + K_);
            float4 h2v = *(const float4*)(ph + 2 * K_);
            float4 h3v = *(const float4*)(ph + 3 * K_);

            // prefetch next weight group (last iter reloads current; harmless)
            const float* pn = (g < 47) ? (pw + 4 * J_) : pw;
            ulonglong2 na0 = *(const ulonglong2*)(pn);
            ulonglong2 nb0 = *(const ulonglong2*)(pn + 4);
            ulonglong2 na1 = *(const ulonglong2*)(pn + J_);
            ulonglong2 nb1 = *(const ulonglong2*)(pn + J_ + 4);
            ulonglong2 na2 = *(const ulonglong2*)(pn + 2 * J_);
            ulonglong2 nb2 = *(const ulonglong2*)(pn + 2 * J_ + 4);
            ulonglong2 na3 = *(const ulonglong2*)(pn + 3 * J_);
            ulonglong2 nb3 = *(const ulonglong2*)(pn + 3 * J_ + 4);

            CKSTEP(wa0, wb0, x);
            CKSTEP(wa1, wb1, y);
            CKSTEP(wa2, wb2, z);
            CKSTEP(wa3, wb3, w);

            wa0 = na0; wb0 = nb0; wa1 = na1; wb1 = nb1;
            wa2 = na2; wb2 = nb2; wa3 = na3; wb3 = nb3;
            pw = pn;
            ph += 4;
        }

        // ---- store partials to zred[ks][b][col] ----
        {
            float* zr = zred + ks * 2048 + lcol;
            *(ulonglong2*)(zr + (bg * 4 + 0) * 128)     = make_ulonglong2(a00, a01);
            *(ulonglong2*)(zr + (bg * 4 + 0) * 128 + 4) = make_ulonglong2(a02, a03);
            *(ulonglong2*)(zr + (bg * 4 + 1) * 128)     = make_ulonglong2(a10, a11);
            *(ulonglong2*)(zr + (bg * 4 + 1) * 128 + 4) = make_ulonglong2(a12, a13);
            *(ulonglong2*)(zr + (bg * 4 + 2) * 128)     = make_ulonglong2(a20, a21);
            *(ulonglong2*)(zr + (bg * 4 + 2) * 128 + 4) = make_ulonglong2(a22, a23);
            *(ulonglong2*)(zr + (bg * 4 + 3) * 128)     = make_ulonglong2(a30, a31);
            *(ulonglong2*)(zr + (bg * 4 + 3) * 128 + 4) = make_ulonglong2(a32, a33);
        }
        __syncthreads();

        // ---- k-split reduce + gates + state update: 2 cells per thread ----
        const float* bv = (t == 0) ? g_B0 : g_BT;
#pragma unroll
        for (int s = 0; s < 2; s++) {
            int cell = tid + s * 256;             // 0..511
            int bl = cell >> 5;
            int ul = cell & 31;
            float zi = 0.f, zf = 0.f, zg = 0.f, zo = 0.f;
#pragma unroll
            for (int kk = 0; kk < 4; kk++) {
                const float* zr = zred + kk * 2048 + bl * 128 + ul;
                zi += zr[0];
                zf += zr[32];
                zg += zr[64];
                zo += zr[96];
            }
            int jb = ut * 32 + ul;
            zi += bv[jb];
            zf += bv[U_ + jb];
            zg += bv[2 * U_ + jb];
            zo += bv[3 * U_ + jb];
            float ig = 1.f / (1.f + expf(-zi));
            float fg = 1.f / (1.f + expf(-zf));
            float gv = tanhf(zg);
            float og = 1.f / (1.f + expf(-zo));
            float cn = fg * cs[cell] + ig * gv;
            cs[cell] = cn;
            float hn = og * tanhf(cn);
            int bglob = bt * 16 + bl;
            int uglob = ut * 32 + ul;
            g_H[(t + 1) & 1][bglob * U_ + uglob] = hn;
            g_Hall[((size_t)t * B_ + bglob) * U_ + uglob] = hn;
        }

        // ---- grid barrier ----
        __threadfence();
        __syncthreads();
        if (tid == 0) {
            unsigned old = atomicAdd(&g_barCount, 1u);
            if (old == (unsigned)(128 * (t + 1) - 1)) {
                g_barPhase = (unsigned)(t + 1);
            } else {
                while (g_barPhase < (unsigned)(t + 1)) { }
            }
            __threadfence();
        }
        __syncthreads();
    }
}

// ---------------- final dense: out[b][t][o] = Hall[t][b] @ dense_w + db ----
__global__ __launch_bounds__(256) void dense_out_k(const float* __restrict__ dw,
                                                   const float* __restrict__ db,
                                                   float* __restrict__ out) {
    __shared__ float hT[32 * 72];
    __shared__ float wT[64 * 64];
    int t = blockIdx.x;
    int b0 = blockIdx.y * 32;
    int tid = threadIdx.x;
    int ol = tid & 31;
    int bg = tid >> 5;
    float a00 = 0, a01 = 0, a10 = 0, a11 = 0, a20 = 0, a21 = 0, a30 = 0, a31 = 0;

    for (int k0 = 0; k0 < U_; k0 += 64) {
        int idx = tid;
#pragma unroll
        for (int it = 0; it < 2; it++, idx += 256) {
            int bl = idx >> 4;
            int kk = (idx & 15) * 4;
            float4 v = *(const float4*)&g_Hall[((size_t)t * B_ + b0 + bl) * U_ + k0 + kk];
            *(float4*)&hT[bl * 72 + kk] = v;
        }
        idx = tid;
#pragma unroll
        for (int it = 0; it < 4; it++, idx += 256) {
            int kk = idx >> 4;
            int oo = (idx & 15) * 4;
            float4 v = *(const float4*)&dw[(k0 + kk) * O_ + oo];
            *(float4*)&wT[kk * 64 + oo] = v;
        }
        __syncthreads();
#pragma unroll 4
        for (int k = 0; k < 64; k++) {
            float w0 = wT[k * 64 + ol];
            float w1 = wT[k * 64 + ol + 32];
            float h0 = hT[(bg * 4 + 0) * 72 + k];
            float h1 = hT[(bg * 4 + 1) * 72 + k];
            float h2 = hT[(bg * 4 + 2) * 72 + k];
            float h3 = hT[(bg * 4 + 3) * 72 + k];
            a00 += h0 * w0; a01 += h0 * w1;
            a10 += h1 * w0; a11 += h1 * w1;
            a20 += h2 * w0; a21 += h2 * w1;
            a30 += h3 * w0; a31 += h3 * w1;
        }
        __syncthreads();
    }
    float d0 = db[ol], d1 = db[ol + 32];
    int b = b0 + bg * 4;
    out[((size_t)(b + 0) * T_ + t) * O_ + ol]      = a00 + d0;
    out[((size_t)(b + 0) * T_ + t) * O_ + ol + 32] = a01 + d1;
    out[((size_t)(b + 1) * T_ + t) * O_ + ol]      = a10 + d0;
    out[((size_t)(b + 1) * T_ + t) * O_ + ol + 32] = a11 + d1;
    out[((size_t)(b + 2) * T_ + t) * O_ + ol]      = a20 + d0;
    out[((size_t)(b + 2) * T_ + t) * O_ + ol + 32] = a21 + d1;
    out[((size_t)(b + 3) * T_ + t) * O_ + ol]      = a30 + d0;
    out[((size_t)(b + 3) * T_ + t) * O_ + ol + 32] = a31 + d1;
}

// ---------------- launch ----------------
extern "C" void kernel_launch(void* const* d_in, const int* in_sizes, int n_in,
                              void* d_out, int out_size) {
    const float* inputs = (const float*)d_in[0];
    const float* kern   = (const float*)d_in[1];
    const float* rec    = (const float*)d_in[2];
    const float* bias   = (const float*)d_in[3];
    const float* dw     = (const float*)d_in[4];
    const float* db     = (const float*)d_in[5];
    float* out = (float*)d_out;

    const size_t smem = (size_t)(16 * K_ + 4 * 16 * 128 + 512) * sizeof(float); // 83968 B
    cudaFuncSetAttribute(lstm_recur, cudaFuncAttributeMaxDynamicSharedMemorySize, (int)smem);

    prep_weights<<<(K_ * J_) / 256, 256>>>(rec, kern, dw);
    prep_misc<<<(J_ + B_ * U_ + 1 + 255) / 256, 256>>>(bias, db, kern);
    lstm_recur<<<128, 256, smem>>>(inputs);
    dense_out_k<<<dim3(T_, 4), 256>>>(dw, db, out);
}